// round 5
// baseline (speedup 1.0000x reference)
#include <cuda_runtime.h>

#define NB 8
#define NP 4096
#define NG 96
#define NT 1024
#define CPT (NP / NT)          // 4 columns per thread in lsa_kernel
#define BIGF 1e9f
#define PCHUNK 128             // p-rows per colmin block

// packed (ordered-float-key<<32 | argmin p) per (batch, gt-row)
__device__ unsigned long long g_min64[NB][NG];

// monotonic unsigned key for float ordering
__device__ __forceinline__ unsigned int fkey(float f) {
    unsigned int b = __float_as_uint(f);
    return b ^ ((b & 0x80000000u) ? 0xFFFFFFFFu : 0x80000000u);
}
__device__ __forceinline__ float funkey(unsigned int k) {
    return __uint_as_float(k ^ ((k & 0x80000000u) ? 0x80000000u : 0xFFFFFFFFu));
}

__device__ __forceinline__ float cost_at(const float* __restrict__ cd,
                                         const float* __restrict__ gi,
                                         int b, int g, int j) {
    size_t idx = ((size_t)(b * NP + j)) * NG + g;
    return cd[idx] - 2.0f * gi[idx];
}

// ---------------------------------------------------------------------------
// Row minima directly from [B,P,G] layout. Block (96,8): threadIdx.x = g
// (coalesced 384B per p-row), threadIdx.y strides over p within the chunk.
// ---------------------------------------------------------------------------
__global__ void colmin_kernel(const float* __restrict__ cd,
                              const float* __restrict__ gi) {
    const int b  = blockIdx.y;
    const int p0 = blockIdx.x * PCHUNK;
    const int g  = threadIdx.x;
    const int r  = threadIdx.y;

    unsigned long long best = ~0ull;
    #pragma unroll
    for (int k = r; k < PCHUNK; k += 8) {
        int p = p0 + k;
        size_t idx = ((size_t)(b * NP + p)) * NG + g;
        float c = cd[idx] - 2.0f * gi[idx];
        unsigned long long pk = ((unsigned long long)fkey(c) << 32) | (unsigned int)p;
        best = min(best, pk);
    }

    __shared__ unsigned long long sm[8][96];
    sm[r][g] = best;
    __syncthreads();
    if (r == 0) {
        #pragma unroll
        for (int q = 1; q < 8; ++q) best = min(best, sm[q][g]);
        atomicMin(&g_min64[b][g], best);
    }
}

// ---------------------------------------------------------------------------
// One CTA per batch: greedy (JV row-reduction) init, then exact shortest
// augmenting path for the few conflicted rows, then scatter epilogue.
// Cost rows are gathered on the fly from the original [B,P,G] layout.
// ---------------------------------------------------------------------------
#define SMEM_BYTES (3*NP*4 /*v,shortest,path(+colwin alias)*/ \
                    + NP*4 /*row4col*/                        \
                    + NG*4*3 /*u,col4row,jmin*/               \
                    + 32*4*2 /*redv,redi*/                    \
                    + NP /*SC*/ + NG /*SR*/ + 16 /*scalars*/)

__global__ void __launch_bounds__(NT, 1)
lsa_kernel(const float* __restrict__ cd, const float* __restrict__ gi,
           const int* __restrict__ nactual, float* __restrict__ out) {
    extern __shared__ unsigned char smem[];
    float* v         = (float*)smem;                   // NP
    float* shortest  = v + NP;                         // NP
    int*   path      = (int*)(shortest + NP);          // NP (reused as colwin)
    int*   row4col   = path + NP;                      // NP
    float* u         = (float*)(row4col + NP);         // NG
    int*   col4row   = (int*)(u + NG);                 // NG
    int*   jmin_s    = col4row + NG;                   // NG
    float* redv      = (float*)(jmin_s + NG);          // 32
    int*   redi      = (int*)(redv + 32);              // 32
    unsigned char* SC = (unsigned char*)(redi + 32);   // NP
    unsigned char* SR = SC + NP;                       // NG
    int*   s_int     = (int*)(SR + NG);                // scalars
    int*   s_cur     = &s_int[0];
    int*   s_sink    = &s_int[1];
    float* s_minval  = (float*)&s_int[2];

    const int b    = blockIdx.x;
    const int tid  = threadIdx.x;
    const int nact = nactual[b];

    // ---- per-batch init + greedy (row-reduction) assignment ----
    int* colwin = path;  // alias during greedy phase
    #pragma unroll
    for (int k = 0; k < CPT; ++k) {
        int j = tid + k * NT;
        v[j] = 0.0f;
        row4col[j] = -1;
        colwin[j] = 0x7fffffff;
    }
    if (tid < NG) {
        unsigned long long pk = g_min64[b][tid];
        u[tid]       = funkey((unsigned int)(pk >> 32));
        jmin_s[tid]  = (int)(unsigned int)(pk & 0xffffffffu);
        col4row[tid] = -1;
    }
    __syncthreads();
    if (tid < nact) atomicMin(&colwin[jmin_s[tid]], tid);
    __syncthreads();
    if (tid < nact) {
        int j = jmin_s[tid];
        if (colwin[j] == tid) {           // lowest claimant wins
            col4row[tid] = j;
            row4col[j]   = tid;
        }
    }
    __syncthreads();

    // ---- shortest augmenting path for each unassigned row ----
    for (int i = 0; i < nact; ++i) {
        if (col4row[i] >= 0) continue;

        #pragma unroll
        for (int k = 0; k < CPT; ++k) {
            int j = tid + k * NT;
            shortest[j] = BIGF;
            path[j] = -1;
            SC[j] = 0;
        }
        if (tid < NG) SR[tid] = 0;
        if (tid == 0) { *s_cur = i; *s_minval = 0.0f; *s_sink = -1; }
        __syncthreads();

        while (true) {
            const int   cur    = *s_cur;
            const float minval = *s_minval;
            if (tid == 0) SR[cur] = 1;
            const float ucur = u[cur];

            float lv = 3.0e38f;
            int   li = NP;
            #pragma unroll
            for (int k = 0; k < CPT; ++k) {
                int j = tid + k * NT;
                float cand;
                if (!SC[j]) {
                    float sh  = shortest[j];
                    float red = ((minval + cost_at(cd, gi, b, cur, j)) - ucur) - v[j];
                    if (red < sh) { sh = red; shortest[j] = red; path[j] = cur; }
                    cand = sh;
                } else {
                    cand = BIGF;
                }
                if (cand < lv) { lv = cand; li = j; }  // ascending j: lowest idx
            }

            #pragma unroll
            for (int off = 16; off > 0; off >>= 1) {
                float ov = __shfl_down_sync(0xffffffffu, lv, off);
                int   oi = __shfl_down_sync(0xffffffffu, li, off);
                if (ov < lv || (ov == lv && oi < li)) { lv = ov; li = oi; }
            }
            const int lane = tid & 31, wid = tid >> 5;
            if (lane == 0) { redv[wid] = lv; redi[wid] = li; }
            __syncthreads();
            if (wid == 0) {
                lv = redv[lane]; li = redi[lane];
                #pragma unroll
                for (int off = 16; off > 0; off >>= 1) {
                    float ov = __shfl_down_sync(0xffffffffu, lv, off);
                    int   oi = __shfl_down_sync(0xffffffffu, li, off);
                    if (ov < lv || (ov == lv && oi < li)) { lv = ov; li = oi; }
                }
                if (lane == 0) {
                    int j = li;
                    *s_minval = lv;
                    SC[j] = 1;
                    int r = row4col[j];
                    if (r < 0) *s_sink = j;
                    else       *s_cur  = r;
                }
            }
            __syncthreads();
            if (*s_sink >= 0) break;
        }

        // ---- dual updates (scipy rectangular_lsap semantics) ----
        const float minval = *s_minval;
        const int   sinkj  = *s_sink;
        if (tid < NG) {
            if (tid == i)      u[tid] = u[tid] + minval;
            else if (SR[tid])  u[tid] = (u[tid] + minval) - shortest[col4row[tid]];
        }
        #pragma unroll
        for (int k = 0; k < CPT; ++k) {
            int j = tid + k * NT;
            if (SC[j]) v[j] = v[j] - (minval - shortest[j]);
        }
        __syncthreads();

        // ---- augment ----
        if (tid == 0) {
            int j = sinkj;
            while (true) {
                int r = path[j];
                row4col[j] = r;
                int jn = col4row[r];
                col4row[r] = j;
                if (r == i) break;
                j = jn;
            }
        }
        __syncthreads();
    }

    // ---- epilogue ----
    float* out_inds = out;                 // [NB*NP] per_prop_gt_inds (as float)
    float* out_mask = out + NB * NP;       // [NB*NP] proposal_matched_mask
    #pragma unroll
    for (int k = 0; k < CPT; ++k) {
        int j = tid + k * NT;
        out_inds[b * NP + j] = 0.0f;
        out_mask[b * NP + j] = 0.0f;
    }
    __syncthreads();
    if (tid < nact) {
        int j = col4row[tid];
        out_inds[b * NP + j] = (float)tid;
        out_mask[b * NP + j] = 1.0f;
    }
}

// ---------------------------------------------------------------------------
extern "C" void kernel_launch(void* const* d_in, const int* in_sizes, int n_in,
                              void* d_out, int out_size) {
    const float* cd   = (const float*)d_in[0];   // center_dist [8,4096,96] f32
    const float* gi   = (const float*)d_in[1];   // gious       [8,4096,96] f32
    const int*   nact = (const int*)d_in[2];     // nactual_gt  [8] i32

    void* min64_addr = nullptr;
    cudaGetSymbolAddress(&min64_addr, g_min64);
    cudaMemsetAsync(min64_addr, 0xFF, sizeof(unsigned long long) * NB * NG);

    colmin_kernel<<<dim3(NP / PCHUNK, NB), dim3(96, 8)>>>(cd, gi);

    cudaFuncSetAttribute(lsa_kernel,
                         cudaFuncAttributeMaxDynamicSharedMemorySize,
                         SMEM_BYTES);
    lsa_kernel<<<NB, NT, SMEM_BYTES>>>(cd, gi, nact, (float*)d_out);
}

// round 8
// speedup vs baseline: 1.2771x; 1.2771x over previous
#include <cuda_runtime.h>

#define NB 8
#define NP 4096
#define NG 96
#define NT 1024
#define CPT (NP / NT)          // 4 columns per thread in lsa_kernel
#define BIGF 1e9f
#define PSLAB 64               // p-rows per build block

// 12.6 MB scratch: transposed cost matrix, L2-resident.
__device__ float g_costT[NB][NG][NP];
// packed (ordered-float-key<<32 | argmin p) per (batch, gt-row)
__device__ unsigned long long g_min64[NB][NG];

// monotonic unsigned key for float ordering
__device__ __forceinline__ unsigned int fkey(float f) {
    unsigned int b = __float_as_uint(f);
    return b ^ ((b & 0x80000000u) ? 0xFFFFFFFFu : 0x80000000u);
}
__device__ __forceinline__ float funkey(unsigned int k) {
    return __uint_as_float(k ^ ((k & 0x80000000u) ? 0x80000000u : 0xFFFFFFFFu));
}

// ---------------------------------------------------------------------------
// Fused: cost = cd - 2*gi, transpose to costT[b][g][p], and per-row (g) min.
// Block: 256 threads, one 64-p slab x all 96 g of one batch.
//   Phase 1: float4 reads (coalesced), scalar stores to padded smem tileT.
//   Phase 2: coalesced writes of costT (p-contiguous per g).
//   Phase 3: threads 0..95 scan their g column (conflict-free), atomicMin.
// ---------------------------------------------------------------------------
__global__ void __launch_bounds__(256, 4)
build_cost_kernel(const float* __restrict__ cd, const float* __restrict__ gi) {
    __shared__ float tileT[NG][PSLAB + 1];   // [g][p_local], pad breaks conflicts

    const int b  = blockIdx.y;
    const int p0 = blockIdx.x * PSLAB;
    const int t  = threadIdx.x;

    // Phase 1: 64 rows * 24 float4 per array = 1536 float4 -> 6 iters/thread
    const float4* cd4 = (const float4*)(cd + ((size_t)(b * NP + p0)) * NG);
    const float4* gi4 = (const float4*)(gi + ((size_t)(b * NP + p0)) * NG);
    #pragma unroll
    for (int it = 0; it < (PSLAB * (NG / 4)) / 256; ++it) {
        int i = t + it * 256;
        int p = i / (NG / 4);
        int k = i % (NG / 4);
        float4 a = cd4[i];
        float4 c = gi4[i];
        int g = 4 * k;
        tileT[g + 0][p] = a.x - 2.0f * c.x;
        tileT[g + 1][p] = a.y - 2.0f * c.y;
        tileT[g + 2][p] = a.z - 2.0f * c.z;
        tileT[g + 3][p] = a.w - 2.0f * c.w;
    }
    __syncthreads();

    // Phase 2: write costT coalesced (p-contiguous within each g)
    #pragma unroll
    for (int it = 0; it < (NG * PSLAB) / 256; ++it) {
        int i = t + it * 256;
        int g = i / PSLAB;
        int p = i % PSLAB;
        g_costT[b][g][p0 + p] = tileT[g][p];
    }

    // Phase 3: per-g min over this slab (threads 0..95; conflict-free columns)
    if (t < NG) {
        unsigned long long best = ~0ull;
        #pragma unroll 8
        for (int p = 0; p < PSLAB; ++p) {
            unsigned long long pk =
                ((unsigned long long)fkey(tileT[t][p]) << 32) | (unsigned int)(p0 + p);
            best = min(best, pk);
        }
        atomicMin(&g_min64[b][t], best);
    }
}

// ---------------------------------------------------------------------------
// One CTA per batch: greedy (JV row-reduction) init, then exact shortest
// augmenting path for the few conflicted rows, then scatter epilogue.
// ---------------------------------------------------------------------------
#define SMEM_BYTES (4*NP*4 /*v,shortest,path(+colwin),row4col*/ \
                    + NG*4*3 /*u,col4row,jmin*/                 \
                    + 32*4*2 /*redv,redi*/                      \
                    + NP /*SC*/ + NG /*SR*/ + 16 /*scalars*/)

__global__ void __launch_bounds__(NT, 1)
lsa_kernel(const int* __restrict__ nactual, float* __restrict__ out) {
    extern __shared__ unsigned char smem[];
    float* v         = (float*)smem;                   // NP
    float* shortest  = v + NP;                         // NP
    int*   path      = (int*)(shortest + NP);          // NP (reused as colwin)
    int*   row4col   = path + NP;                      // NP
    float* u         = (float*)(row4col + NP);         // NG
    int*   col4row   = (int*)(u + NG);                 // NG
    int*   jmin_s    = col4row + NG;                   // NG
    float* redv      = (float*)(jmin_s + NG);          // 32
    int*   redi      = (int*)(redv + 32);              // 32
    unsigned char* SC = (unsigned char*)(redi + 32);   // NP
    unsigned char* SR = SC + NP;                       // NG
    int*   s_int     = (int*)(SR + NG);                // scalars
    int*   s_cur     = &s_int[0];
    int*   s_sink    = &s_int[1];
    float* s_minval  = (float*)&s_int[2];

    const int b    = blockIdx.x;
    const int tid  = threadIdx.x;
    const int nact = nactual[b];

    // ---- per-batch init + greedy (row-reduction) assignment ----
    int* colwin = path;  // alias during greedy phase
    #pragma unroll
    for (int k = 0; k < CPT; ++k) {
        int j = tid + k * NT;
        v[j] = 0.0f;
        row4col[j] = -1;
        colwin[j] = 0x7fffffff;
    }
    if (tid < NG) {
        unsigned long long pk = g_min64[b][tid];
        u[tid]       = funkey((unsigned int)(pk >> 32));
        jmin_s[tid]  = (int)(unsigned int)(pk & 0xffffffffu);
        col4row[tid] = -1;
    }
    __syncthreads();
    if (tid < nact) atomicMin(&colwin[jmin_s[tid]], tid);
    __syncthreads();
    if (tid < nact) {
        int j = jmin_s[tid];
        if (colwin[j] == tid) {           // lowest claimant wins
            col4row[tid] = j;
            row4col[j]   = tid;
        }
    }
    __syncthreads();

    // ---- shortest augmenting path for each unassigned row ----
    for (int i = 0; i < nact; ++i) {
        if (col4row[i] >= 0) continue;

        #pragma unroll
        for (int k = 0; k < CPT; ++k) {
            int j = tid + k * NT;
            shortest[j] = BIGF;
            path[j] = -1;
            SC[j] = 0;
        }
        if (tid < NG) SR[tid] = 0;
        if (tid == 0) { *s_cur = i; *s_minval = 0.0f; *s_sink = -1; }
        __syncthreads();

        while (true) {
            const int   cur    = *s_cur;
            const float minval = *s_minval;
            if (tid == 0) SR[cur] = 1;
            const float ucur = u[cur];
            const float* __restrict__ crow = &g_costT[b][cur][0];

            float lv = 3.0e38f;
            int   li = NP;
            #pragma unroll
            for (int k = 0; k < CPT; ++k) {
                int j = tid + k * NT;
                float cand;
                if (!SC[j]) {
                    float sh  = shortest[j];
                    float red = ((minval + crow[j]) - ucur) - v[j];
                    if (red < sh) { sh = red; shortest[j] = red; path[j] = cur; }
                    cand = sh;
                } else {
                    cand = BIGF;
                }
                if (cand < lv) { lv = cand; li = j; }  // ascending j: lowest idx
            }

            #pragma unroll
            for (int off = 16; off > 0; off >>= 1) {
                float ov = __shfl_down_sync(0xffffffffu, lv, off);
                int   oi = __shfl_down_sync(0xffffffffu, li, off);
                if (ov < lv || (ov == lv && oi < li)) { lv = ov; li = oi; }
            }
            const int lane = tid & 31, wid = tid >> 5;
            if (lane == 0) { redv[wid] = lv; redi[wid] = li; }
            __syncthreads();
            if (wid == 0) {
                lv = redv[lane]; li = redi[lane];
                #pragma unroll
                for (int off = 16; off > 0; off >>= 1) {
                    float ov = __shfl_down_sync(0xffffffffu, lv, off);
                    int   oi = __shfl_down_sync(0xffffffffu, li, off);
                    if (ov < lv || (ov == lv && oi < li)) { lv = ov; li = oi; }
                }
                if (lane == 0) {
                    int j = li;
                    *s_minval = lv;
                    SC[j] = 1;
                    int r = row4col[j];
                    if (r < 0) *s_sink = j;
                    else       *s_cur  = r;
                }
            }
            __syncthreads();
            if (*s_sink >= 0) break;
        }

        // ---- dual updates (scipy rectangular_lsap semantics) ----
        const float minval = *s_minval;
        const int   sinkj  = *s_sink;
        if (tid < NG) {
            if (tid == i)      u[tid] = u[tid] + minval;
            else if (SR[tid])  u[tid] = (u[tid] + minval) - shortest[col4row[tid]];
        }
        #pragma unroll
        for (int k = 0; k < CPT; ++k) {
            int j = tid + k * NT;
            if (SC[j]) v[j] = v[j] - (minval - shortest[j]);
        }
        __syncthreads();

        // ---- augment ----
        if (tid == 0) {
            int j = sinkj;
            while (true) {
                int r = path[j];
                row4col[j] = r;
                int jn = col4row[r];
                col4row[r] = j;
                if (r == i) break;
                j = jn;
            }
        }
        __syncthreads();
    }

    // ---- epilogue ----
    float* out_inds = out;                 // [NB*NP] per_prop_gt_inds (as float)
    float* out_mask = out + NB * NP;       // [NB*NP] proposal_matched_mask
    #pragma unroll
    for (int k = 0; k < CPT; ++k) {
        int j = tid + k * NT;
        out_inds[b * NP + j] = 0.0f;
        out_mask[b * NP + j] = 0.0f;
    }
    __syncthreads();
    if (tid < nact) {
        int j = col4row[tid];
        out_inds[b * NP + j] = (float)tid;
        out_mask[b * NP + j] = 1.0f;
    }
}

// ---------------------------------------------------------------------------
extern "C" void kernel_launch(void* const* d_in, const int* in_sizes, int n_in,
                              void* d_out, int out_size) {
    const float* cd   = (const float*)d_in[0];   // center_dist [8,4096,96] f32
    const float* gi   = (const float*)d_in[1];   // gious       [8,4096,96] f32
    const int*   nact = (const int*)d_in[2];     // nactual_gt  [8] i32

    void* min64_addr = nullptr;
    cudaGetSymbolAddress(&min64_addr, g_min64);
    cudaMemsetAsync(min64_addr, 0xFF, sizeof(unsigned long long) * NB * NG);

    build_cost_kernel<<<dim3(NP / PSLAB, NB), 256>>>(cd, gi);

    cudaFuncSetAttribute(lsa_kernel,
                         cudaFuncAttributeMaxDynamicSharedMemorySize,
                         SMEM_BYTES);
    lsa_kernel<<<NB, NT, SMEM_BYTES>>>(nact, (float*)d_out);
}

// round 9
// speedup vs baseline: 1.2790x; 1.0015x over previous
#include <cuda_runtime.h>

#define NB 8
#define NP 4096
#define NG 96
#define BIGF 1e9f
#define PSLAB 64               // p-rows per build block
#define NT2 256                // lsa block size
#define CPT2 (NP / NT2)        // 16 columns per thread

// 12.6 MB scratch: transposed cost matrix, L2-resident.
__device__ float g_costT[NB][NG][NP];
// packed (ordered-float-key<<32 | argmin p) per (batch, gt-row)
__device__ unsigned long long g_min64[NB][NG];

// monotonic unsigned key for float ordering
__device__ __forceinline__ unsigned int fkey(float f) {
    unsigned int b = __float_as_uint(f);
    return b ^ ((b & 0x80000000u) ? 0xFFFFFFFFu : 0x80000000u);
}
__device__ __forceinline__ float funkey(unsigned int k) {
    return __uint_as_float(k ^ ((k & 0x80000000u) ? 0x80000000u : 0xFFFFFFFFu));
}

// ---------------------------------------------------------------------------
// Fused: cost = cd - 2*gi, transpose to costT[b][g][p], and per-row (g) min.
// ---------------------------------------------------------------------------
__global__ void __launch_bounds__(256, 4)
build_cost_kernel(const float* __restrict__ cd, const float* __restrict__ gi) {
    __shared__ float tileT[NG][PSLAB + 1];

    const int b  = blockIdx.y;
    const int p0 = blockIdx.x * PSLAB;
    const int t  = threadIdx.x;

    const float4* cd4 = (const float4*)(cd + ((size_t)(b * NP + p0)) * NG);
    const float4* gi4 = (const float4*)(gi + ((size_t)(b * NP + p0)) * NG);
    #pragma unroll
    for (int it = 0; it < (PSLAB * (NG / 4)) / 256; ++it) {
        int i = t + it * 256;
        int p = i / (NG / 4);
        int k = i % (NG / 4);
        float4 a = cd4[i];
        float4 c = gi4[i];
        int g = 4 * k;
        tileT[g + 0][p] = a.x - 2.0f * c.x;
        tileT[g + 1][p] = a.y - 2.0f * c.y;
        tileT[g + 2][p] = a.z - 2.0f * c.z;
        tileT[g + 3][p] = a.w - 2.0f * c.w;
    }
    __syncthreads();

    #pragma unroll
    for (int it = 0; it < (NG * PSLAB) / 256; ++it) {
        int i = t + it * 256;
        int g = i / PSLAB;
        int p = i % PSLAB;
        g_costT[b][g][p0 + p] = tileT[g][p];
    }

    if (t < NG) {
        unsigned long long best = ~0ull;
        #pragma unroll 8
        for (int p = 0; p < PSLAB; ++p) {
            unsigned long long pk =
                ((unsigned long long)fkey(tileT[t][p]) << 32) | (unsigned int)(p0 + p);
            best = min(best, pk);
        }
        atomicMin(&g_min64[b][t], best);
    }
}

// ---------------------------------------------------------------------------
// One CTA (256 threads) per batch. Thread t owns columns j = 4t + 1024k + m,
// k=0..3, m=0..3 (bit = 4k+m). shortest/v/SC live in registers.
// ---------------------------------------------------------------------------
__global__ void __launch_bounds__(NT2, 1)
lsa_kernel(const int* __restrict__ nactual, float* __restrict__ out) {
    __shared__ int   path[NP];          // predecessor row per col (alias colwin)
    __shared__ int   row4col[NP];
    __shared__ float u[NG];
    __shared__ int   col4row[NG];
    __shared__ int   jmin_s[NG];
    __shared__ float rvals[NG];         // entry value of each scanned row
    __shared__ unsigned char SRf[NG];
    __shared__ int   selj[NG + 32];     // selected columns (<= NG+1)
    __shared__ float selv[NG + 32];
    __shared__ float redv[8];
    __shared__ int   redi[8];
    __shared__ int   s_cur, s_sink, s_selj, s_nsel;
    __shared__ float s_minval;

    const int b    = blockIdx.x;
    const int t    = threadIdx.x;
    const int nact = nactual[b];

    float vv[16];                       // register v for owned columns
    #pragma unroll
    for (int q = 0; q < 16; ++q) vv[q] = 0.0f;

    // ---- per-batch init + greedy (JV row-reduction) assignment ----
    int* colwin = path;
    #pragma unroll
    for (int it = 0; it < NP / NT2; ++it) {
        int j = t + it * NT2;
        row4col[j] = -1;
        colwin[j] = 0x7fffffff;
    }
    if (t < NG) {
        unsigned long long pk = g_min64[b][t];
        u[t]       = funkey((unsigned int)(pk >> 32));
        jmin_s[t]  = (int)(unsigned int)(pk & 0xffffffffu);
        col4row[t] = -1;
    }
    __syncthreads();
    if (t < nact) atomicMin(&colwin[jmin_s[t]], t);
    __syncthreads();
    if (t < nact) {
        int j = jmin_s[t];
        if (colwin[j] == t) {            // lowest claimant wins
            col4row[t] = j;
            row4col[j] = t;
        }
    }
    __syncthreads();

    // ---- shortest augmenting path for each unassigned row ----
    for (int i = 0; i < nact; ++i) {
        if (col4row[i] >= 0) continue;

        float sh[16];
        #pragma unroll
        for (int q = 0; q < 16; ++q) sh[q] = BIGF;
        unsigned int scmask = 0;

        if (t < NG) SRf[t] = (t == i) ? 1 : 0;
        if (t == 0) { s_cur = i; s_minval = 0.0f; s_sink = -1; s_nsel = 0; }
        __syncthreads();

        while (true) {
            const int   cur    = s_cur;
            const float minval = s_minval;
            const float ucur   = u[cur];
            const float4* __restrict__ crow4 = (const float4*)&g_costT[b][cur][0];

            float lv = 3.0e38f;
            int   li = NP;
            #pragma unroll
            for (int k = 0; k < 4; ++k) {
                float4 c = crow4[t + NT2 * k];
                float cm[4] = {c.x, c.y, c.z, c.w};
                #pragma unroll
                for (int m = 0; m < 4; ++m) {
                    const int bit = 4 * k + m;
                    if (!((scmask >> bit) & 1u)) {
                        float red = ((minval + cm[m]) - ucur) - vv[bit];
                        int j = 4 * t + 1024 * k + m;
                        if (red < sh[bit]) { sh[bit] = red; path[j] = cur; }
                        if (sh[bit] < lv) { lv = sh[bit]; li = j; }  // ascending j
                    }
                }
            }

            // warp argmin, then 8-entry final by thread 0
            #pragma unroll
            for (int off = 16; off > 0; off >>= 1) {
                float ov = __shfl_down_sync(0xffffffffu, lv, off);
                int   oi = __shfl_down_sync(0xffffffffu, li, off);
                if (ov < lv || (ov == lv && oi < li)) { lv = ov; li = oi; }
            }
            if ((t & 31) == 0) { redv[t >> 5] = lv; redi[t >> 5] = li; }
            __syncthreads();
            if (t == 0) {
                lv = redv[0]; li = redi[0];
                #pragma unroll
                for (int w = 1; w < 8; ++w) {
                    if (redv[w] < lv || (redv[w] == lv && redi[w] < li)) {
                        lv = redv[w]; li = redi[w];
                    }
                }
                s_minval = lv;
                s_selj   = li;
                int ns = s_nsel;
                selj[ns] = li; selv[ns] = lv; s_nsel = ns + 1;
                int r = row4col[li];
                if (r < 0) { s_sink = li; }
                else       { s_cur = r; rvals[r] = lv; SRf[r] = 1; }
            }
            __syncthreads();
            {   // owner marks selected column scanned
                int jw = s_selj;
                if (((jw & 1023) >> 2) == t)
                    scmask |= 1u << (((jw >> 10) << 2) | (jw & 3));
            }
            if (s_sink >= 0) break;
        }

        // ---- dual updates (scipy rectangular_lsap semantics) ----
        const float minval = s_minval;
        const int   ns     = s_nsel;
        const int   sinkj  = s_sink;
        if (t < NG) {
            if (t == i)       u[t] = u[t] + minval;
            else if (SRf[t])  u[t] = (u[t] + minval) - rvals[t];
        }
        for (int e = 0; e < ns; ++e) {
            int j = selj[e];
            if (((j & 1023) >> 2) == t) {
                int bit = ((j >> 10) << 2) | (j & 3);
                float d = minval - selv[e];
                #pragma unroll
                for (int q = 0; q < 16; ++q)
                    if (q == bit) vv[q] = vv[q] - d;
            }
        }
        __syncthreads();

        // ---- augment: flip alternating path from sink back to row i ----
        if (t == 0) {
            int j = sinkj;
            while (true) {
                int r = path[j];
                row4col[j] = r;
                int jn = col4row[r];
                col4row[r] = j;
                if (r == i) break;
                j = jn;
            }
        }
        __syncthreads();
    }

    // ---- epilogue ----
    float* out_inds = out;                 // [NB*NP] per_prop_gt_inds (as float)
    float* out_mask = out + NB * NP;       // [NB*NP] proposal_matched_mask
    float4 z4 = make_float4(0.f, 0.f, 0.f, 0.f);
    float4* oi4 = (float4*)(out_inds + b * NP);
    float4* om4 = (float4*)(out_mask + b * NP);
    #pragma unroll
    for (int it = 0; it < NP / 4 / NT2; ++it) {
        oi4[t + it * NT2] = z4;
        om4[t + it * NT2] = z4;
    }
    __syncthreads();
    if (t < nact) {
        int j = col4row[t];
        out_inds[b * NP + j] = (float)t;
        out_mask[b * NP + j] = 1.0f;
    }
}

// ---------------------------------------------------------------------------
extern "C" void kernel_launch(void* const* d_in, const int* in_sizes, int n_in,
                              void* d_out, int out_size) {
    const float* cd   = (const float*)d_in[0];   // center_dist [8,4096,96] f32
    const float* gi   = (const float*)d_in[1];   // gious       [8,4096,96] f32
    const int*   nact = (const int*)d_in[2];     // nactual_gt  [8] i32

    void* min64_addr = nullptr;
    cudaGetSymbolAddress(&min64_addr, g_min64);
    cudaMemsetAsync(min64_addr, 0xFF, sizeof(unsigned long long) * NB * NG);

    build_cost_kernel<<<dim3(NP / PSLAB, NB), 256>>>(cd, gi);

    lsa_kernel<<<NB, NT2>>>(nact, (float*)d_out);
}